// round 12
// baseline (speedup 1.0000x reference)
#include <cuda_runtime.h>

// Fixed shapes: B=2, D=1024, L=2048, NH=8 -> H=128
#define B_   2
#define D_   1024
#define L_   2048
#define NH   8
#define H_   128
#define TLL  512          // l-tile per block: 128 threads x 4 consecutive l each
#define TM   128          // m-tile
#define KOFF 640          // zeros before lag 0 in g_kf rows
#define KPAD 2816         // padded filter row length
#define KSMS 656          // k smem floats per stage
#define NST  3            // pipeline stages

typedef unsigned long long u64;

// Forward zero-padded filter: g_kf[h][KOFF+lag] = k[h][lag] (0 <= lag < L), else 0
__device__ __align__(16) float g_kf[H_ * KPAD];

__device__ __forceinline__ u64 pack2(float x, float y) {
    u64 r; asm("mov.b64 %0, {%1,%2};" : "=l"(r) : "f"(x), "f"(y)); return r;
}
__device__ __forceinline__ float lo2(u64 v) {
    float x, y; asm("mov.b64 {%0,%1}, %2;" : "=f"(x), "=f"(y) : "l"(v)); return x;
}
__device__ __forceinline__ float hsum2(u64 v) {
    float x, y; asm("mov.b64 {%0,%1}, %2;" : "=f"(x), "=f"(y) : "l"(v)); return x + y;
}
__device__ __forceinline__ u64 fma2(u64 a, u64 b, u64 c) {
    u64 d; asm("fma.rn.f32x2 %0, %1, %2, %3;" : "=l"(d) : "l"(a), "l"(b), "l"(c)); return d;
}
__device__ __forceinline__ u64 mul2(u64 a, u64 b) {
    u64 d; asm("mul.rn.f32x2 %0, %1, %2;" : "=l"(d) : "l"(a), "l"(b)); return d;
}
__device__ __forceinline__ u64 ll(double d) { return __double_as_longlong(d); }
__device__ __forceinline__ void cpasync16(void* dst, const void* src) {
    unsigned d = (unsigned)__cvta_generic_to_shared(dst);
    asm volatile("cp.async.ca.shared.global [%0], [%1], 16;" :: "r"(d), "l"(src));
}

__global__ void build_kf(const float* __restrict__ k) {
    int idx = blockIdx.x * 256 + threadIdx.x;
    if (idx >= H_ * KPAD) return;
    int h = idx / KPAD, j = idx % KPAD;
    int lag = j - KOFF;
    g_kf[idx] = (lag >= 0 && lag < L_) ? k[h * L_ + lag] : 0.0f;
}

__global__ void __launch_bounds__(128, 3)
hyena_conv_kernel(const float* __restrict__ v,
                  const float* __restrict__ bias,
                  const float* __restrict__ x1,
                  const float* __restrict__ x2,
                  float* __restrict__ out)
{
    __shared__ __align__(16) float vsm [NST][NH][TM];    // [stage][i][m]
    __shared__ __align__(16) float x2sm[NST][NH][TM];    // [stage][j][m]
    __shared__ __align__(16) float ksm[NST][KSMS];       // [stage] filter window
    __shared__ float bsm[NH];

    const int tid = threadIdx.x;
    const int wid = tid >> 5;
    const int blk = blockIdx.x;
    const int bh  = blk & 255;            // b*H_ + h
    const int lt  = 3 - (blk >> 8);       // LPT: heavy l-tiles first
    const int h   = bh & 127;
    const int b   = bh >> 7;
    const int L0  = lt * TLL;
    const int l0  = L0 + 4 * tid;         // this thread's 4 l's: l0..l0+3

    const float* vb  = v  + ((size_t)b * D_ + (size_t)h * NH) * L_;
    const float* x1b = x1 + ((size_t)b * D_ + (size_t)h * NH) * L_;
    const float* x2b = x2 + ((size_t)b * D_ + (size_t)h * NH) * L_;
    float*       ob  = out + ((size_t)b * D_ + (size_t)h * NH) * L_;
    const float* kptr = g_kf + (size_t)h * KPAD + (KOFF + L0 - 132);

    const int nmt = (L0 + TLL) / TM;      // 4,8,12,16

    const int c0i = tid >> 5,         c0m = (tid & 31) << 2;
    const int c1i = (tid + 128) >> 5, c1m = (tid & 31) << 2;
    auto issue = [&](int mt_, int p) {
        const int M0 = mt_ * TM;
        cpasync16(&vsm [p][c0i][c0m], vb  + c0i * L_ + M0 + c0m);
        cpasync16(&x2sm[p][c0i][c0m], x2b + c0i * L_ + M0 + c0m);
        cpasync16(&vsm [p][c1i][c1m], vb  + c1i * L_ + M0 + c1m);
        cpasync16(&x2sm[p][c1i][c1m], x2b + c1i * L_ + M0 + c1m);
        const float* src = kptr - M0;
        cpasync16(&ksm[p][tid * 4], src + tid * 4);
        if (tid < (KSMS - 512) / 4) cpasync16(&ksm[p][(tid + 128) * 4], src + (tid + 128) * 4);
        asm volatile("cp.async.commit_group;" ::: "memory");
    };

    issue(0, 0);
    issue(1, 1);

    if (tid < NH) bsm[tid] = bias[h * NH + tid];

    // x1 gates for 4 l's: resident splats for dl 0,1; scalars for dl 2,3
    u64 x1p0[NH], x1p1[NH];
    float x1v2[NH], x1v3[NH];
    #pragma unroll
    for (int i = 0; i < NH; i++) {
        float4 q = *(const float4*)&x1b[i * L_ + l0];
        x1p0[i] = pack2(q.x, q.x);
        x1p1[i] = pack2(q.y, q.y);
        x1v2[i] = q.z; x1v3[i] = q.w;
    }

    u64 acc[4][NH];                       // [dl][j], lanes = (even m, odd m)
    #pragma unroll
    for (int dl = 0; dl < 4; dl++)
        #pragma unroll
        for (int j = 0; j < NH; j++) acc[dl][j] = 0;

    int pc = 0;                 // current stage
    int pi = 2;                 // next stage to fill
    for (int mt = 0; mt < nmt; mt++) {
        if (mt == nmt - 1) asm volatile("cp.async.wait_group 0;" ::: "memory");
        else               asm volatile("cp.async.wait_group 1;" ::: "memory");
        __syncthreads();        // single barrier per tile (NST=3 ring)

        const int base = L0 - mt * TM;

        // whole-warp causal skip; when not skipped the tile is always FULL (trip 32)
        if (base + 128 * wid + 128 > 0) {
            const float (*vt)[TM]  = vsm[pc];
            const float (*x2t)[TM] = x2sm[pc];
            const float* cw = &ksm[pc][128 + 4 * tid];   // tap window base

            #pragma unroll 4
            for (int mi = 0; mi < TM; mi += 4) {
                // filter window c[0..7] = taps for 4 l's x 4 m's (2 aligned LDS.128)
                float4 ca = *(const float4*)(cw - mi);
                float4 cb = *(const float4*)(cw - mi + 4);

                // s[dl][mpair] = sum_i x1[i, l0+dl] * v[i, m-pair]
                u64 s0[4], s1[4];
                {
                    double2 vq = *(const double2*)&vt[0][mi];
                    u64 vlo = ll(vq.x), vhi = ll(vq.y);
                    u64 e2 = pack2(x1v2[0], x1v2[0]), e3 = pack2(x1v3[0], x1v3[0]);
                    s0[0] = mul2(x1p0[0], vlo); s1[0] = mul2(x1p0[0], vhi);
                    s0[1] = mul2(x1p1[0], vlo); s1[1] = mul2(x1p1[0], vhi);
                    s0[2] = mul2(e2,      vlo); s1[2] = mul2(e2,      vhi);
                    s0[3] = mul2(e3,      vlo); s1[3] = mul2(e3,      vhi);
                }
                #pragma unroll
                for (int i = 1; i < NH; i++) {
                    double2 vq = *(const double2*)&vt[i][mi];
                    u64 vlo = ll(vq.x), vhi = ll(vq.y);
                    u64 e2 = pack2(x1v2[i], x1v2[i]), e3 = pack2(x1v3[i], x1v3[i]);
                    s0[0] = fma2(x1p0[i], vlo, s0[0]); s1[0] = fma2(x1p0[i], vhi, s1[0]);
                    s0[1] = fma2(x1p1[i], vlo, s0[1]); s1[1] = fma2(x1p1[i], vhi, s1[1]);
                    s0[2] = fma2(e2,      vlo, s0[2]); s1[2] = fma2(e2,      vhi, s1[2]);
                    s0[3] = fma2(e3,      vlo, s0[3]); s1[3] = fma2(e3,      vhi, s1[3]);
                }

                // Toeplitz taps: lane tap = c[4 + dl - dm]
                // mpair0 (dm=0,1): (c[4+dl], c[3+dl]); mpair1 (dm=2,3): (c[2+dl], c[1+dl])
                s0[0] = mul2(pack2(cb.x, ca.w), s0[0]); s1[0] = mul2(pack2(ca.z, ca.y), s1[0]);
                s0[1] = mul2(pack2(cb.y, cb.x), s0[1]); s1[1] = mul2(pack2(ca.w, ca.z), s1[1]);
                s0[2] = mul2(pack2(cb.z, cb.y), s0[2]); s1[2] = mul2(pack2(cb.x, ca.w), s1[2]);
                s0[3] = mul2(pack2(cb.w, cb.z), s0[3]); s1[3] = mul2(pack2(cb.y, cb.x), s1[3]);

                // acc[dl][j] += t[dl] .* x2[j, m-pairs]
                #pragma unroll
                for (int j = 0; j < NH; j++) {
                    double2 xq = *(const double2*)&x2t[j][mi];
                    u64 xlo = ll(xq.x), xhi = ll(xq.y);
                    #pragma unroll
                    for (int dl = 0; dl < 4; dl++) {
                        acc[dl][j] = fma2(s0[dl], xlo, acc[dl][j]);
                        acc[dl][j] = fma2(s1[dl], xhi, acc[dl][j]);
                    }
                }
            }
        }

        if (mt + 2 < nmt) issue(mt + 2, pi);
        if (++pc == NST) pc = 0;
        if (++pi == NST) pi = 0;
    }

    // Epilogue: horizontal add + skip/bias term, vectorized float4 store.
    float sb0 = 0.f, sb1 = 0.f, sb2 = 0.f, sb3 = 0.f;
    #pragma unroll
    for (int i = 0; i < NH; i++) {
        float4 vv = *(const float4*)&vb[i * L_ + l0];
        float bw = bsm[i];
        sb0 += lo2(x1p0[i]) * bw * vv.x;
        sb1 += lo2(x1p1[i]) * bw * vv.y;
        sb2 += x1v2[i]      * bw * vv.z;
        sb3 += x1v3[i]      * bw * vv.w;
    }
    #pragma unroll
    for (int j = 0; j < NH; j++) {
        float4 xx = *(const float4*)&x2b[j * L_ + l0];
        float4 o;
        o.x = hsum2(acc[0][j]) + sb0 * xx.x;
        o.y = hsum2(acc[1][j]) + sb1 * xx.y;
        o.z = hsum2(acc[2][j]) + sb2 * xx.z;
        o.w = hsum2(acc[3][j]) + sb3 * xx.w;
        *(float4*)&ob[j * L_ + l0] = o;
    }
}

extern "C" void kernel_launch(void* const* d_in, const int* in_sizes, int n_in,
                              void* d_out, int out_size)
{
    const float* v    = (const float*)d_in[0];
    const float* k    = (const float*)d_in[1];
    const float* bias = (const float*)d_in[2];
    const float* x1   = (const float*)d_in[3];
    const float* x2   = (const float*)d_in[4];
    float* out = (float*)d_out;

    build_kf<<<(H_ * KPAD + 255) / 256, 256>>>(k);
    dim3 grid(B_ * H_ * (L_ / TLL));   // 1024 blocks, heavy l-tiles first
    hyena_conv_kernel<<<grid, 128>>>(v, bias, x1, x2, out);
}

// round 13
// speedup vs baseline: 1.1379x; 1.1379x over previous
#include <cuda_runtime.h>

// Fixed shapes: B=2, D=1024, L=2048, NH=8 -> H=128
#define B_   2
#define D_   1024
#define L_   2048
#define NH   8
#define H_   128
#define TLL  256          // l-tile per block: 128 threads x 2 l (l0=L0+2t, l1=l0+1)
#define TM   128          // m-tile
#define KR2  2720         // padded reversed-filter row length
#define KWIN 392          // k smem window floats per stage per copy
#define NST  3            // pipeline stages

typedef unsigned long long u64;

// Reversed zero-padded filter copies:
//   g_kra[h][u] = kval(h, 2306 - u),  g_krb[h][u] = kval(h, 2307 - u)
__device__ __align__(16) float g_kra[H_ * KR2];
__device__ __align__(16) float g_krb[H_ * KR2];

__device__ __forceinline__ u64 pack2(float x, float y) {
    u64 r; asm("mov.b64 %0, {%1,%2};" : "=l"(r) : "f"(x), "f"(y)); return r;
}
__device__ __forceinline__ float lo2(u64 v) {
    float x, y; asm("mov.b64 {%0,%1}, %2;" : "=f"(x), "=f"(y) : "l"(v)); return x;
}
__device__ __forceinline__ float hsum2(u64 v) {
    float x, y; asm("mov.b64 {%0,%1}, %2;" : "=f"(x), "=f"(y) : "l"(v)); return x + y;
}
__device__ __forceinline__ u64 fma2(u64 a, u64 b, u64 c) {
    u64 d; asm("fma.rn.f32x2 %0, %1, %2, %3;" : "=l"(d) : "l"(a), "l"(b), "l"(c)); return d;
}
__device__ __forceinline__ u64 mul2(u64 a, u64 b) {
    u64 d; asm("mul.rn.f32x2 %0, %1, %2;" : "=l"(d) : "l"(a), "l"(b)); return d;
}
__device__ __forceinline__ u64 ll(double d) { return __double_as_longlong(d); }
__device__ __forceinline__ void cpasync16(void* dst, const void* src) {
    unsigned d = (unsigned)__cvta_generic_to_shared(dst);
    asm volatile("cp.async.ca.shared.global [%0], [%1], 16;" :: "r"(d), "l"(src));
}

__global__ void build_kr(const float* __restrict__ k) {
    int idx = blockIdx.x * 256 + threadIdx.x;
    if (idx >= H_ * KR2) return;
    int h = idx / KR2, u = idx % KR2;
    int a  = (L_ + 258) - u;       // 2306 - u
    int a2 = a + 1;
    g_kra[idx] = (a  >= 0 && a  < L_) ? k[h * L_ + a ] : 0.0f;
    g_krb[idx] = (a2 >= 0 && a2 < L_) ? k[h * L_ + a2] : 0.0f;
}

// Compile-time trip-count tile body: MM is 128 or 64 (constants only).
// Unroll 8 => 8 independent 4m-steps in the scheduler window.
#define COMPUTE_TILE(MM)                                                     \
    _Pragma("unroll 8")                                                      \
    for (int mm = 0; mm < (MM); mm += 4) {                                   \
        u64 sA0, sA1, sB0, sB1;                                              \
        {                                                                    \
            double2 vq = *(const double2*)&vt[0][mm];                        \
            u64 vlo = ll(vq.x), vhi = ll(vq.y);                              \
            sA0 = mul2(x1A[0], vlo); sA1 = mul2(x1A[0], vhi);                \
            sB0 = mul2(x1B[0], vlo); sB1 = mul2(x1B[0], vhi);                \
        }                                                                    \
        _Pragma("unroll")                                                    \
        for (int i = 1; i < NH; i++) {                                       \
            double2 vq = *(const double2*)&vt[i][mm];                        \
            u64 vlo = ll(vq.x), vhi = ll(vq.y);                              \
            sA0 = fma2(x1A[i], vlo, sA0); sA1 = fma2(x1A[i], vhi, sA1);      \
            sB0 = fma2(x1B[i], vlo, sB0); sB1 = fma2(x1B[i], vhi, sB1);      \
        }                                                                    \
        u64 tA0 = mul2(*(const u64*)(kap + mm),     sA0);                    \
        u64 tA1 = mul2(*(const u64*)(kap + mm + 2), sA1);                    \
        u64 tB0 = mul2(*(const u64*)(kbp + mm),     sB0);                    \
        u64 tB1 = mul2(*(const u64*)(kbp + mm + 2), sB1);                    \
        _Pragma("unroll")                                                    \
        for (int j = 0; j < NH; j++) {                                       \
            double2 xq = *(const double2*)&x2t[j][mm];                       \
            u64 xlo = ll(xq.x), xhi = ll(xq.y);                              \
            accA[j] = fma2(tA0, xlo, accA[j]);                               \
            accB[j] = fma2(tB0, xlo, accB[j]);                               \
            accA[j] = fma2(tA1, xhi, accA[j]);                               \
            accB[j] = fma2(tB1, xhi, accB[j]);                               \
        }                                                                    \
    }

__global__ void __launch_bounds__(128, 4)
hyena_conv_kernel(const float* __restrict__ v,
                  const float* __restrict__ bias,
                  const float* __restrict__ x1,
                  const float* __restrict__ x2,
                  float* __restrict__ out)
{
    __shared__ __align__(16) float vsm [NST][NH][TM];
    __shared__ __align__(16) float x2sm[NST][NH][TM];
    __shared__ __align__(16) float wa[NST][KWIN];
    __shared__ __align__(16) float wb[NST][KWIN];
    __shared__ float bsm[NH];

    const int tid = threadIdx.x;
    const int wid = tid >> 5;
    const int blk = blockIdx.x;
    const int bh  = blk & 255;
    const int lt  = 7 - (blk >> 8);       // LPT: heavy l-tiles first
    const int h   = bh & 127;
    const int b   = bh >> 7;
    const int L0  = lt * TLL;
    const int l0  = L0 + 2 * tid;

    const float* vb  = v  + ((size_t)b * D_ + (size_t)h * NH) * L_;
    const float* x1b = x1 + ((size_t)b * D_ + (size_t)h * NH) * L_;
    const float* x2b = x2 + ((size_t)b * D_ + (size_t)h * NH) * L_;
    float*       ob  = out + ((size_t)b * D_ + (size_t)h * NH) * L_;
    const float* kra = g_kra + (size_t)h * KR2;
    const float* krb = g_krb + (size_t)h * KR2;

    const int nmt = L0 / TM + 2;

    const int c0i = tid >> 5,         c0m = (tid & 31) << 2;
    const int c1i = (tid + 128) >> 5, c1m = (tid & 31) << 2;
    auto issue = [&](int mt_, int p) {
        const int M0 = mt_ * TM;
        cpasync16(&vsm [p][c0i][c0m], vb  + c0i * L_ + M0 + c0m);
        cpasync16(&x2sm[p][c0i][c0m], x2b + c0i * L_ + M0 + c0m);
        cpasync16(&vsm [p][c1i][c1m], vb  + c1i * L_ + M0 + c1m);
        cpasync16(&x2sm[p][c1i][c1m], x2b + c1i * L_ + M0 + c1m);
        const int u0 = L_ - L0 + M0;
        if (tid < KWIN / 4) {
            cpasync16(&wa[p][tid * 4], kra + u0 + tid * 4);
            cpasync16(&wb[p][tid * 4], krb + u0 + tid * 4);
        }
        asm volatile("cp.async.commit_group;" ::: "memory");
    };

    issue(0, 0);
    issue(1, 1);

    if (tid < NH) bsm[tid] = bias[h * NH + tid];

    // x1 gate splats for l0, l1
    u64 x1A[NH], x1B[NH];
    #pragma unroll
    for (int i = 0; i < NH; i++) {
        float2 q = *(const float2*)&x1b[i * L_ + l0];
        x1A[i] = pack2(q.x, q.x);
        x1B[i] = pack2(q.y, q.y);
    }

    u64 accA[NH], accB[NH];
    #pragma unroll
    for (int j = 0; j < NH; j++) { accA[j] = 0; accB[j] = 0; }

    const int soff = 258 - 2 * tid;

    int pc = 0;                 // current stage
    int pi = 2;                 // next stage to fill
    for (int mt = 0; mt < nmt; mt++) {
        if (mt == nmt - 1) asm volatile("cp.async.wait_group 0;" ::: "memory");
        else               asm volatile("cp.async.wait_group 1;" ::: "memory");
        __syncthreads();

        const int base  = L0 - mt * TM;
        const int mmaxw = min(TM, base + 64 * wid + 64);   // always in {0, 64, 128}

        if (mmaxw > 0) {
            const float (*vt)[TM]  = vsm[pc];
            const float (*x2t)[TM] = x2sm[pc];
            const float* kap = &wa[pc][soff];
            const float* kbp = &wb[pc][soff];

            if (mmaxw == TM) {          // full tile: compile-time trip count 32
                COMPUTE_TILE(TM)
            } else {                    // diagonal half tile: trip count 16
                COMPUTE_TILE(64)
            }
        }

        if (mt + 2 < nmt) issue(mt + 2, pi);
        if (++pc == NST) pc = 0;
        if (++pi == NST) pi = 0;
    }

    // Epilogue: horizontal add + skip/bias term, float2 stores.
    float sbA = 0.f, sbB = 0.f;
    #pragma unroll
    for (int i = 0; i < NH; i++) {
        float2 vv = *(const float2*)&vb[i * L_ + l0];
        float bw = bsm[i];
        sbA += lo2(x1A[i]) * bw * vv.x;
        sbB += lo2(x1B[i]) * bw * vv.y;
    }
    #pragma unroll
    for (int j = 0; j < NH; j++) {
        float2 xx = *(const float2*)&x2b[j * L_ + l0];
        float2 o;
        o.x = hsum2(accA[j]) + sbA * xx.x;
        o.y = hsum2(accB[j]) + sbB * xx.y;
        *(float2*)&ob[j * L_ + l0] = o;
    }
}

extern "C" void kernel_launch(void* const* d_in, const int* in_sizes, int n_in,
                              void* d_out, int out_size)
{
    const float* v    = (const float*)d_in[0];
    const float* k    = (const float*)d_in[1];
    const float* bias = (const float*)d_in[2];
    const float* x1   = (const float*)d_in[3];
    const float* x2   = (const float*)d_in[4];
    float* out = (float*)d_out;

    build_kr<<<(H_ * KR2 + 255) / 256, 256>>>(k);
    dim3 grid(B_ * H_ * (L_ / TLL));   // 2048 blocks, heavy l-tiles first
    hyena_conv_kernel<<<grid, 128>>>(v, bias, x1, x2, out);
}

// round 14
// speedup vs baseline: 1.1498x; 1.0105x over previous
#include <cuda_runtime.h>

// Fixed shapes: B=2, D=1024, L=2048, NH=8 -> H=128
#define B_   2
#define D_   1024
#define L_   2048
#define NH   8
#define H_   128
#define TLL  256          // l-tile per block: 128 threads x 2 l (l0=L0+2t, l1=l0+1)
#define TM   128          // m-tile
#define KR2  2720         // padded reversed-filter row length
#define KWIN 392          // k smem window floats per stage
#define NST  3            // pipeline stages

typedef unsigned long long u64;

// Reversed zero-padded filter: g_kra[h][u] = kval(h, 2306 - u),
// where kval(h,a) = k[h][a] for 0<=a<L, else 0.
__device__ __align__(16) float g_kra[H_ * KR2];

__device__ __forceinline__ u64 pack2(float x, float y) {
    u64 r; asm("mov.b64 %0, {%1,%2};" : "=l"(r) : "f"(x), "f"(y)); return r;
}
__device__ __forceinline__ float lo2(u64 v) {
    float x, y; asm("mov.b64 {%0,%1}, %2;" : "=f"(x), "=f"(y) : "l"(v)); return x;
}
__device__ __forceinline__ float hi2(u64 v) {
    float x, y; asm("mov.b64 {%0,%1}, %2;" : "=f"(x), "=f"(y) : "l"(v)); return y;
}
__device__ __forceinline__ float hsum2(u64 v) {
    float x, y; asm("mov.b64 {%0,%1}, %2;" : "=f"(x), "=f"(y) : "l"(v)); return x + y;
}
__device__ __forceinline__ u64 fma2(u64 a, u64 b, u64 c) {
    u64 d; asm("fma.rn.f32x2 %0, %1, %2, %3;" : "=l"(d) : "l"(a), "l"(b), "l"(c)); return d;
}
__device__ __forceinline__ u64 mul2(u64 a, u64 b) {
    u64 d; asm("mul.rn.f32x2 %0, %1, %2;" : "=l"(d) : "l"(a), "l"(b)); return d;
}
__device__ __forceinline__ u64 ll(double d) { return __double_as_longlong(d); }
__device__ __forceinline__ void cpasync16(void* dst, const void* src) {
    unsigned d = (unsigned)__cvta_generic_to_shared(dst);
    asm volatile("cp.async.ca.shared.global [%0], [%1], 16;" :: "r"(d), "l"(src));
}

__global__ void build_kr(const float* __restrict__ k) {
    int idx = blockIdx.x * 256 + threadIdx.x;
    if (idx >= H_ * KR2) return;
    int h = idx / KR2, u = idx % KR2;
    int a = (L_ + 258) - u;        // 2306 - u
    g_kra[idx] = (a >= 0 && a < L_) ? k[h * L_ + a] : 0.0f;
}

// Compile-time trip-count tile body: MM is 128 or 64 (constants only).
// B-lane taps are derived from A-lane tap registers via a 1-value loop carry
// (kbp[s] == kap[s-1]) -- saves 2 LDS.64 (4 wavefronts) per 4m-step.
#define COMPUTE_TILE(MM)                                                     \
    u64 kpn = *(const u64*)(kap - 2);                                        \
    _Pragma("unroll 8")                                                      \
    for (int mm = 0; mm < (MM); mm += 4) {                                   \
        u64 kc = *(const u64*)(kap + mm);                                    \
        u64 kn = *(const u64*)(kap + mm + 2);                                \
        u64 sA0, sA1, sB0, sB1;                                              \
        {                                                                    \
            double2 vq = *(const double2*)&vt[0][mm];                        \
            u64 vlo = ll(vq.x), vhi = ll(vq.y);                              \
            sA0 = mul2(x1A[0], vlo); sA1 = mul2(x1A[0], vhi);                \
            sB0 = mul2(x1B[0], vlo); sB1 = mul2(x1B[0], vhi);                \
        }                                                                    \
        _Pragma("unroll")                                                    \
        for (int i = 1; i < NH; i++) {                                       \
            double2 vq = *(const double2*)&vt[i][mm];                        \
            u64 vlo = ll(vq.x), vhi = ll(vq.y);                              \
            sA0 = fma2(x1A[i], vlo, sA0); sA1 = fma2(x1A[i], vhi, sA1);      \
            sB0 = fma2(x1B[i], vlo, sB0); sB1 = fma2(x1B[i], vhi, sB1);      \
        }                                                                    \
        u64 tA0 = mul2(kc, sA0);                                             \
        u64 tA1 = mul2(kn, sA1);                                             \
        u64 tB0 = mul2(pack2(hi2(kpn), lo2(kc)), sB0);                       \
        u64 tB1 = mul2(pack2(hi2(kc),  lo2(kn)), sB1);                       \
        kpn = kn;                                                            \
        _Pragma("unroll")                                                    \
        for (int j = 0; j < NH; j++) {                                       \
            double2 xq = *(const double2*)&x2t[j][mm];                       \
            u64 xlo = ll(xq.x), xhi = ll(xq.y);                              \
            accA[j] = fma2(tA0, xlo, accA[j]);                               \
            accB[j] = fma2(tB0, xlo, accB[j]);                               \
            accA[j] = fma2(tA1, xhi, accA[j]);                               \
            accB[j] = fma2(tB1, xhi, accB[j]);                               \
        }                                                                    \
    }

__global__ void __launch_bounds__(128, 4)
hyena_conv_kernel(const float* __restrict__ v,
                  const float* __restrict__ bias,
                  const float* __restrict__ x1,
                  const float* __restrict__ x2,
                  float* __restrict__ out)
{
    __shared__ __align__(16) float vsm [NST][NH][TM];
    __shared__ __align__(16) float x2sm[NST][NH][TM];
    __shared__ __align__(16) float wa[NST][KWIN];
    __shared__ float bsm[NH];

    const int tid = threadIdx.x;
    const int wid = tid >> 5;
    const int blk = blockIdx.x;
    const int bh  = blk & 255;
    const int lt  = 7 - (blk >> 8);       // LPT: heavy l-tiles first
    const int h   = bh & 127;
    const int b   = bh >> 7;
    const int L0  = lt * TLL;
    const int l0  = L0 + 2 * tid;

    const float* vb  = v  + ((size_t)b * D_ + (size_t)h * NH) * L_;
    const float* x1b = x1 + ((size_t)b * D_ + (size_t)h * NH) * L_;
    const float* x2b = x2 + ((size_t)b * D_ + (size_t)h * NH) * L_;
    float*       ob  = out + ((size_t)b * D_ + (size_t)h * NH) * L_;
    const float* kra = g_kra + (size_t)h * KR2;

    const int nmt = L0 / TM + 2;

    const int c0i = tid >> 5,         c0m = (tid & 31) << 2;
    const int c1i = (tid + 128) >> 5, c1m = (tid & 31) << 2;
    auto issue = [&](int mt_, int p) {
        const int M0 = mt_ * TM;
        cpasync16(&vsm [p][c0i][c0m], vb  + c0i * L_ + M0 + c0m);
        cpasync16(&x2sm[p][c0i][c0m], x2b + c0i * L_ + M0 + c0m);
        cpasync16(&vsm [p][c1i][c1m], vb  + c1i * L_ + M0 + c1m);
        cpasync16(&x2sm[p][c1i][c1m], x2b + c1i * L_ + M0 + c1m);
        const int u0 = L_ - L0 + M0;
        if (tid < KWIN / 4) cpasync16(&wa[p][tid * 4], kra + u0 + tid * 4);
        asm volatile("cp.async.commit_group;" ::: "memory");
    };

    issue(0, 0);
    issue(1, 1);

    if (tid < NH) bsm[tid] = bias[h * NH + tid];

    // x1 gate splats for l0, l1
    u64 x1A[NH], x1B[NH];
    #pragma unroll
    for (int i = 0; i < NH; i++) {
        float2 q = *(const float2*)&x1b[i * L_ + l0];
        x1A[i] = pack2(q.x, q.x);
        x1B[i] = pack2(q.y, q.y);
    }

    u64 accA[NH], accB[NH];
    #pragma unroll
    for (int j = 0; j < NH; j++) { accA[j] = 0; accB[j] = 0; }

    const int soff = 258 - 2 * tid;

    int pc = 0;                 // current stage
    int pi = 2;                 // next stage to fill
    for (int mt = 0; mt < nmt; mt++) {
        if (mt == nmt - 1) asm volatile("cp.async.wait_group 0;" ::: "memory");
        else               asm volatile("cp.async.wait_group 1;" ::: "memory");
        __syncthreads();

        // issue the mt+2 tile BEFORE compute: stage pi was consumed at tile mt-1,
        // which all warps finished before the barrier above.
        if (mt + 2 < nmt) issue(mt + 2, pi);

        const int base  = L0 - mt * TM;
        const int mmaxw = min(TM, base + 64 * wid + 64);   // always in {0, 64, 128}

        if (mmaxw > 0) {
            const float (*vt)[TM]  = vsm[pc];
            const float (*x2t)[TM] = x2sm[pc];
            const float* kap = &wa[pc][soff];

            if (mmaxw == TM) {          // full tile: compile-time trip count 32
                COMPUTE_TILE(TM)
            } else {                    // diagonal half tile: trip count 16
                COMPUTE_TILE(64)
            }
        }

        if (++pc == NST) pc = 0;
        if (++pi == NST) pi = 0;
    }

    // Epilogue: horizontal add + skip/bias term, float2 stores.
    float sbA = 0.f, sbB = 0.f;
    #pragma unroll
    for (int i = 0; i < NH; i++) {
        float2 vv = *(const float2*)&vb[i * L_ + l0];
        float bw = bsm[i];
        sbA += lo2(x1A[i]) * bw * vv.x;
        sbB += lo2(x1B[i]) * bw * vv.y;
    }
    #pragma unroll
    for (int j = 0; j < NH; j++) {
        float2 xx = *(const float2*)&x2b[j * L_ + l0];
        float2 o;
        o.x = hsum2(accA[j]) + sbA * xx.x;
        o.y = hsum2(accB[j]) + sbB * xx.y;
        *(float2*)&ob[j * L_ + l0] = o;
    }
}

extern "C" void kernel_launch(void* const* d_in, const int* in_sizes, int n_in,
                              void* d_out, int out_size)
{
    const float* v    = (const float*)d_in[0];
    const float* k    = (const float*)d_in[1];
    const float* bias = (const float*)d_in[2];
    const float* x1   = (const float*)d_in[3];
    const float* x2   = (const float*)d_in[4];
    float* out = (float*)d_out;

    build_kr<<<(H_ * KR2 + 255) / 256, 256>>>(k);
    dim3 grid(B_ * H_ * (L_ / TLL));   // 2048 blocks, heavy l-tiles first
    hyena_conv_kernel<<<grid, 128>>>(v, bias, x1, x2, out);
}

// round 15
// speedup vs baseline: 1.1513x; 1.0013x over previous
#include <cuda_runtime.h>

// Fixed shapes: B=2, D=1024, L=2048, NH=8 -> H=128
#define B_   2
#define D_   1024
#define L_   2048
#define NH   8
#define H_   128
#define TLL  256          // l-tile per block: 128 threads x 2 l (l0=L0+2t, l1=l0+1)
#define TMX  256          // m-tile (doubled: half the barriers)
#define KR2  2720         // padded reversed-filter row length
#define KWIN 520          // k smem window floats per stage
#define NST  2            // pipeline stages

typedef unsigned long long u64;

// Reversed zero-padded filter: g_kra[h][u] = kval(h, 2306 - u),
// where kval(h,a) = k[h][a] for 0<=a<L, else 0.
__device__ __align__(16) float g_kra[H_ * KR2];

__device__ __forceinline__ u64 pack2(float x, float y) {
    u64 r; asm("mov.b64 %0, {%1,%2};" : "=l"(r) : "f"(x), "f"(y)); return r;
}
__device__ __forceinline__ float lo2(u64 v) {
    float x, y; asm("mov.b64 {%0,%1}, %2;" : "=f"(x), "=f"(y) : "l"(v)); return x;
}
__device__ __forceinline__ float hi2(u64 v) {
    float x, y; asm("mov.b64 {%0,%1}, %2;" : "=f"(x), "=f"(y) : "l"(v)); return y;
}
__device__ __forceinline__ float hsum2(u64 v) {
    float x, y; asm("mov.b64 {%0,%1}, %2;" : "=f"(x), "=f"(y) : "l"(v)); return x + y;
}
__device__ __forceinline__ u64 fma2(u64 a, u64 b, u64 c) {
    u64 d; asm("fma.rn.f32x2 %0, %1, %2, %3;" : "=l"(d) : "l"(a), "l"(b), "l"(c)); return d;
}
__device__ __forceinline__ u64 mul2(u64 a, u64 b) {
    u64 d; asm("mul.rn.f32x2 %0, %1, %2;" : "=l"(d) : "l"(a), "l"(b)); return d;
}
__device__ __forceinline__ u64 ll(double d) { return __double_as_longlong(d); }
__device__ __forceinline__ void cpasync16(void* dst, const void* src) {
    unsigned d = (unsigned)__cvta_generic_to_shared(dst);
    asm volatile("cp.async.ca.shared.global [%0], [%1], 16;" :: "r"(d), "l"(src));
}

__global__ void build_kr(const float* __restrict__ k) {
    int idx = blockIdx.x * 256 + threadIdx.x;
    if (idx >= H_ * KR2) return;
    int h = idx / KR2, u = idx % KR2;
    int a = (L_ + 258) - u;        // 2306 - u
    g_kra[idx] = (a >= 0 && a < L_) ? k[h * L_ + a] : 0.0f;
}

// Tile body. MM must be a multiple of 32 (unroll 8 x 4m, no remainder).
// B-lane taps derived from A-lane tap registers via 1-value loop carry.
#define COMPUTE_TILE(MM)                                                     \
    u64 kpn = *(const u64*)(kap - 2);                                        \
    _Pragma("unroll 8")                                                      \
    for (int mm = 0; mm < (MM); mm += 4) {                                   \
        u64 kc = *(const u64*)(kap + mm);                                    \
        u64 kn = *(const u64*)(kap + mm + 2);                                \
        u64 sA0, sA1, sB0, sB1;                                              \
        {                                                                    \
            double2 vq = *(const double2*)&vt[0][mm];                        \
            u64 vlo = ll(vq.x), vhi = ll(vq.y);                              \
            sA0 = mul2(x1A[0], vlo); sA1 = mul2(x1A[0], vhi);                \
            sB0 = mul2(x1B[0], vlo); sB1 = mul2(x1B[0], vhi);                \
        }                                                                    \
        _Pragma("unroll")                                                    \
        for (int i = 1; i < NH; i++) {                                       \
            double2 vq = *(const double2*)&vt[i][mm];                        \
            u64 vlo = ll(vq.x), vhi = ll(vq.y);                              \
            sA0 = fma2(x1A[i], vlo, sA0); sA1 = fma2(x1A[i], vhi, sA1);      \
            sB0 = fma2(x1B[i], vlo, sB0); sB1 = fma2(x1B[i], vhi, sB1);      \
        }                                                                    \
        u64 tA0 = mul2(kc, sA0);                                             \
        u64 tA1 = mul2(kn, sA1);                                             \
        u64 tB0 = mul2(pack2(hi2(kpn), lo2(kc)), sB0);                       \
        u64 tB1 = mul2(pack2(hi2(kc),  lo2(kn)), sB1);                       \
        kpn = kn;                                                            \
        _Pragma("unroll")                                                    \
        for (int j = 0; j < NH; j++) {                                       \
            double2 xq = *(const double2*)&x2t[j][mm];                       \
            u64 xlo = ll(xq.x), xhi = ll(xq.y);                              \
            accA[j] = fma2(tA0, xlo, accA[j]);                               \
            accB[j] = fma2(tB0, xlo, accB[j]);                               \
            accA[j] = fma2(tA1, xhi, accA[j]);                               \
            accB[j] = fma2(tB1, xhi, accB[j]);                               \
        }                                                                    \
    }

__global__ void __launch_bounds__(128, 4)
hyena_conv_kernel(const float* __restrict__ v,
                  const float* __restrict__ bias,
                  const float* __restrict__ x1,
                  const float* __restrict__ x2,
                  float* __restrict__ out)
{
    __shared__ __align__(16) float vsm [NST][NH][TMX];
    __shared__ __align__(16) float x2sm[NST][NH][TMX];
    __shared__ __align__(16) float wa[NST][KWIN];
    __shared__ float bsm[NH];

    const int tid = threadIdx.x;
    const int wid = tid >> 5;
    const int blk = blockIdx.x;
    const int bh  = blk & 255;
    const int lt  = 7 - (blk >> 8);       // LPT: heavy l-tiles first
    const int h   = bh & 127;
    const int b   = bh >> 7;
    const int L0  = lt * TLL;
    const int l0  = L0 + 2 * tid;

    const float* vb  = v  + ((size_t)b * D_ + (size_t)h * NH) * L_;
    const float* x1b = x1 + ((size_t)b * D_ + (size_t)h * NH) * L_;
    const float* x2b = x2 + ((size_t)b * D_ + (size_t)h * NH) * L_;
    float*       ob  = out + ((size_t)b * D_ + (size_t)h * NH) * L_;
    const float* kra = g_kra + (size_t)h * KR2;

    const int nmt = lt + 1;               // m-tiles (TMX=256): 1..8

    auto issue = [&](int mt_, int p) {
        const int M0 = mt_ * TMX;
        #pragma unroll
        for (int q = 0; q < 4; q++) {
            int f = tid + 128 * q;                 // 0..511 chunk id
            int i = f >> 6, c = (f & 63) << 2;
            cpasync16(&vsm [p][i][c], vb  + i * L_ + M0 + c);
            cpasync16(&x2sm[p][i][c], x2b + i * L_ + M0 + c);
        }
        const int u0 = L_ - L0 + M0;               // >= 256, u0+519 < KR2
        cpasync16(&wa[p][tid * 4], kra + u0 + tid * 4);
        if (tid < 2) cpasync16(&wa[p][(128 + tid) * 4], kra + u0 + (128 + tid) * 4);
        asm volatile("cp.async.commit_group;" ::: "memory");
    };

    issue(0, 0);

    if (tid < NH) bsm[tid] = bias[h * NH + tid];

    // x1 gate splats for l0, l1
    u64 x1A[NH], x1B[NH];
    #pragma unroll
    for (int i = 0; i < NH; i++) {
        float2 q = *(const float2*)&x1b[i * L_ + l0];
        x1A[i] = pack2(q.x, q.x);
        x1B[i] = pack2(q.y, q.y);
    }

    u64 accA[NH], accB[NH];
    #pragma unroll
    for (int j = 0; j < NH; j++) { accA[j] = 0; accB[j] = 0; }

    const int soff = 258 - 2 * tid;       // taps: kap[mm] = kval(l0 - M0 - mm)

    for (int mt = 0; mt < nmt; mt++) {
        asm volatile("cp.async.wait_group 0;" ::: "memory");
        __syncthreads();

        // stage (mt+1)&1 was consumed at tile mt-1 (fenced by the barrier above):
        // issue next tile before compute so the load overlaps this tile fully.
        if (mt + 1 < nmt) issue(mt + 1, (mt + 1) & 1);

        const int p = mt & 1;
        const float (*vt)[TMX]  = vsm[p];
        const float (*x2t)[TMX] = x2sm[p];
        const float* kap = &wa[p][soff];

        if (mt < nmt - 1) {
            // interior tile: always full, compile-time trip count 64
            COMPUTE_TILE(TMX)
        } else {
            // diagonal tile (base = 0): per-warp triangular bound, multiple of 64
            const int mmaxw = 64 * wid + 64;
            COMPUTE_TILE(mmaxw)
        }
    }

    // Epilogue: horizontal add + skip/bias term, float2 stores.
    float sbA = 0.f, sbB = 0.f;
    #pragma unroll
    for (int i = 0; i < NH; i++) {
        float2 vv = *(const float2*)&vb[i * L_ + l0];
        float bw = bsm[i];
        sbA += lo2(x1A[i]) * bw * vv.x;
        sbB += lo2(x1B[i]) * bw * vv.y;
    }
    #pragma unroll
    for (int j = 0; j < NH; j++) {
        float2 xx = *(const float2*)&x2b[j * L_ + l0];
        float2 o;
        o.x = hsum2(accA[j]) + sbA * xx.x;
        o.y = hsum2(accB[j]) + sbB * xx.y;
        *(float2*)&ob[j * L_ + l0] = o;
    }
}

extern "C" void kernel_launch(void* const* d_in, const int* in_sizes, int n_in,
                              void* d_out, int out_size)
{
    const float* v    = (const float*)d_in[0];
    const float* k    = (const float*)d_in[1];
    const float* bias = (const float*)d_in[2];
    const float* x1   = (const float*)d_in[3];
    const float* x2   = (const float*)d_in[4];
    float* out = (float*)d_out;

    build_kr<<<(H_ * KR2 + 255) / 256, 256>>>(k);
    dim3 grid(B_ * H_ * (L_ / TLL));   // 2048 blocks, heavy l-tiles first
    hyena_conv_kernel<<<grid, 128>>>(v, bias, x1, x2, out);
}